// round 10
// baseline (speedup 1.0000x reference)
#include <cuda_runtime.h>
#include <cuda_fp16.h>

// ---------------------------------------------------------------------------
// 2-layer LSTM decoder. Round-10 = Round-4 (proven best) + fp16 recurrent
// weights (halves L2 weight traffic, the diagnosed bottleneck) + streaming
// cache hints on output/eps (protect L2 weight residency).
// 256 CTAs x 32 rows x 512 threads, 4 barriers/step, fused projection.
// ---------------------------------------------------------------------------

#define ULL unsigned long long
#define T_STEPS 20
#define HP 36   // h row stride (floats): 16B-aligned, broadcast LDS.128 reads
#define CP 33   // c row stride: odd -> conflict-free per-thread access

__device__ __forceinline__ ULL pack2(float x, float y) {
    ULL r; asm("mov.b64 %0, {%1, %2};" : "=l"(r) : "f"(x), "f"(y)); return r;
}
__device__ __forceinline__ float2 unpack2(ULL v) {
    float2 r; asm("mov.b64 {%0, %1}, %2;" : "=f"(r.x), "=f"(r.y) : "l"(v)); return r;
}
__device__ __forceinline__ ULL fma2(ULL a, ULL b, ULL c) {
    ULL d; asm("fma.rn.f32x2 %0, %1, %2, %3;" : "=l"(d) : "l"(a), "l"(b), "l"(c)); return d;
}
__device__ __forceinline__ float sigf(float x)  { return __fdividef(1.f, 1.f + __expf(-x)); }
__device__ __forceinline__ float tanhe(float x) { return __fdividef(2.f, 1.f + __expf(-2.f * x)) - 1.f; }

__device__ __forceinline__ uint h2u(__half2 h) { return *reinterpret_cast<uint*>(&h); }
__device__ __forceinline__ __half2 u2h(uint v) { return *reinterpret_cast<__half2*>(&v); }

__device__ float4 g_w1q [64  * 256];          // W1 gate quads (fp32, xw1 precompute)
__device__ uint2  g_u1h [256 * 256];          // U1 fp16 quads: {(i,f),(g,o)}
__device__ uint4  g_wv2h[256 * 256];          // {W2(i,f),W2(g,o),U2(i,f),U2(g,o)} fp16
__device__ float2 g_pw2 [256 * 80 + 80];      // (Wmu, Wlv) fp32 pairs [k][f]
__device__ float4 g_xw1q[8192 * 256];         // xw1 quads [row][u], bias folded (fp32)

__global__ void repack_kernel(const float* __restrict__ W1, const float* __restrict__ U1,
                              const float* __restrict__ W2, const float* __restrict__ U2,
                              const float* __restrict__ Wmu, const float* __restrict__ Wlv) {
    int i = blockIdx.x * blockDim.x + threadIdx.x;   // 0..65535
    int k = i >> 8, u = i & 255;
    const float* r;
    if (i < 64 * 256) {
        r = W1 + k * 1024;
        g_w1q[i] = make_float4(r[u], r[256 + u], r[512 + u], r[768 + u]);
    }
    r = U1 + k * 1024;
    g_u1h[i] = make_uint2(h2u(__floats2half2_rn(r[u],       r[256 + u])),
                          h2u(__floats2half2_rn(r[512 + u], r[768 + u])));
    {
        const float* w = W2 + k * 1024;
        const float* v = U2 + k * 1024;
        g_wv2h[i] = make_uint4(h2u(__floats2half2_rn(w[u],       w[256 + u])),
                               h2u(__floats2half2_rn(w[512 + u], w[768 + u])),
                               h2u(__floats2half2_rn(v[u],       v[256 + u])),
                               h2u(__floats2half2_rn(v[512 + u], v[768 + u])));
    }
    if (u < 80) g_pw2[k * 80 + u] = make_float2(Wmu[k * 80 + u], Wlv[k * 80 + u]);
}

__global__ void xw1_kernel(const float* __restrict__ z1, const float* __restrict__ z2,
                           const float* __restrict__ b1) {
    __shared__ float zt[8][64];
    const int tid = threadIdx.x;
    const int rb  = blockIdx.x * 8;
    for (int i = tid; i < 512; i += 256) {
        int r = i >> 6, k = i & 63;
        zt[r][k] = (k < 32) ? z1[(rb + r) * 32 + k] : z2[(rb + r) * 32 + (k - 32)];
    }
    __syncthreads();
    const int u = tid;
    float4 acc[8];
    #pragma unroll
    for (int r = 0; r < 8; r++) acc[r] = make_float4(0.f, 0.f, 0.f, 0.f);
    for (int k = 0; k < 64; k++) {
        float4 w = g_w1q[k * 256 + u];
        #pragma unroll
        for (int r = 0; r < 8; r++) {
            float zv = zt[r][k];
            acc[r].x += zv * w.x; acc[r].y += zv * w.y;
            acc[r].z += zv * w.z; acc[r].w += zv * w.w;
        }
    }
    float4 bq = make_float4(b1[u], b1[256 + u], b1[512 + u], b1[768 + u]);
    #pragma unroll
    for (int r = 0; r < 8; r++)
        g_xw1q[(size_t)(rb + r) * 256 + u] =
            make_float4(acc[r].x + bq.x, acc[r].y + bq.y, acc[r].z + bq.z, acc[r].w + bq.w);
}

// SMEM: h1s/h2s [256][HP], c1s/c2s [256][CP]
#define SMEM_FLOATS (2 * 256 * HP + 2 * 256 * CP)
#define SMEM_BYTES  (SMEM_FLOATS * 4)

__global__ void __launch_bounds__(512, 1) lstm_kernel(
    const float* __restrict__ b2, const float* __restrict__ bmu, const float* __restrict__ blv,
    const float* __restrict__ eps, float* __restrict__ out)
{
    extern __shared__ float sm[];
    float* h1s = sm;
    float* h2s = sm + 256 * HP;
    float* c1s = sm + 2 * 256 * HP;
    float* c2s = c1s + 256 * CP;

    const int tid = threadIdx.x;
    const int u   = tid & 255;
    const int rg  = tid >> 8;
    const int r0  = rg * 16;
    const int rb  = blockIdx.x * 32;

    for (int i = tid; i < SMEM_FLOATS; i += 512) sm[i] = 0.f;
    __syncthreads();

    const float b2i = b2[u], b2f = b2[256 + u], b2g = b2[512 + u], b2o = b2[768 + u];

    // fused proj+sampler mapping: 320 threads = 80 features x 4 row groups of 8
    const bool  pact = tid < 320;
    const int   pf   = pact ? (tid % 80) : 0;
    const int   pgp  = pact ? (tid / 80) : 0;
    const int   pr0  = pgp * 8;
    const float pbmu = pact ? bmu[pf] : 0.f;
    const float pblv = pact ? blv[pf] : 0.f;

    const float4* xq = g_xw1q + (size_t)(rb + r0) * 256 + u;

    ULL acc[4][8];

    for (int t = 0; t < T_STEPS; t++) {
        // ================= layer 1: acc = xw1 + h1 @ U1 =================
        #pragma unroll
        for (int p = 0; p < 8; p++) {
            float4 q0 = xq[(2 * p) * 256];
            float4 q1 = xq[(2 * p + 1) * 256];
            acc[0][p] = pack2(q0.x, q1.x);
            acc[1][p] = pack2(q0.y, q1.y);
            acc[2][p] = pack2(q0.z, q1.z);
            acc[3][p] = pack2(q0.w, q1.w);
        }
        {
            const char* hb = (const char*)(h1s + r0);
            #pragma unroll 2
            for (int k = 0; k < 256; k++) {
                uint2 wq = g_u1h[k * 256 + u];           // fp16 quad, LDG.64
                float2 fif = __half22float2(u2h(wq.x));  // (i,f)
                float2 fgo = __half22float2(u2h(wq.y));  // (g,o)
                ULL wi = pack2(fif.x, fif.x), wf = pack2(fif.y, fif.y);
                ULL wg = pack2(fgo.x, fgo.x), wo = pack2(fgo.y, fgo.y);
                const ulonglong2* hp = (const ulonglong2*)(hb + (size_t)k * (HP * 4));
                ulonglong2 a0 = hp[0], a1 = hp[1];
                #pragma unroll
                for (int p = 0; p < 4; p++) {
                    ULL hv = (p == 0) ? a0.x : (p == 1) ? a0.y : (p == 2) ? a1.x : a1.y;
                    acc[0][p] = fma2(hv, wi, acc[0][p]);
                    acc[1][p] = fma2(hv, wf, acc[1][p]);
                    acc[2][p] = fma2(hv, wg, acc[2][p]);
                    acc[3][p] = fma2(hv, wo, acc[3][p]);
                }
                ulonglong2 a2 = hp[2], a3 = hp[3];
                #pragma unroll
                for (int p = 4; p < 8; p++) {
                    ULL hv = (p == 4) ? a2.x : (p == 5) ? a2.y : (p == 6) ? a3.x : a3.y;
                    acc[0][p] = fma2(hv, wi, acc[0][p]);
                    acc[1][p] = fma2(hv, wf, acc[1][p]);
                    acc[2][p] = fma2(hv, wg, acc[2][p]);
                    acc[3][p] = fma2(hv, wo, acc[3][p]);
                }
            }
        }
        __syncthreads();                                     // (1) GEMV1 reads done
        #pragma unroll
        for (int p = 0; p < 8; p++) {
            float2 iv = unpack2(acc[0][p]);
            float2 fv = unpack2(acc[1][p]);
            float2 gv = unpack2(acc[2][p]);
            float2 ov = unpack2(acc[3][p]);
            int rr = r0 + 2 * p;
            float c0 = c1s[u * CP + rr], c1 = c1s[u * CP + rr + 1];
            c0 = sigf(fv.x) * c0 + sigf(iv.x) * tanhe(gv.x);
            c1 = sigf(fv.y) * c1 + sigf(iv.y) * tanhe(gv.y);
            c1s[u * CP + rr]     = c0;
            c1s[u * CP + rr + 1] = c1;
            *(float2*)(h1s + u * HP + rr) =
                make_float2(sigf(ov.x) * tanhe(c0), sigf(ov.y) * tanhe(c1));
        }
        __syncthreads();                                     // (2) h1_new visible

        // ======== layer 2: acc = b2 + h1_new @ W2 + h2 @ U2 ========
        #pragma unroll
        for (int p = 0; p < 8; p++) {
            acc[0][p] = pack2(b2i, b2i);
            acc[1][p] = pack2(b2f, b2f);
            acc[2][p] = pack2(b2g, b2g);
            acc[3][p] = pack2(b2o, b2o);
        }
        {
            const char* hb1 = (const char*)(h1s + r0);
            const char* hb2 = (const char*)(h2s + r0);
            #pragma unroll 2
            for (int k = 0; k < 256; k++) {
                uint4 wq = g_wv2h[k * 256 + u];          // fp16 W2+U2 quads, LDG.128
                float2 wif = __half22float2(u2h(wq.x));
                float2 wgo = __half22float2(u2h(wq.y));
                float2 vif = __half22float2(u2h(wq.z));
                float2 vgo = __half22float2(u2h(wq.w));
                ULL wi = pack2(wif.x, wif.x), wf = pack2(wif.y, wif.y);
                ULL wg = pack2(wgo.x, wgo.x), wo = pack2(wgo.y, wgo.y);
                ULL vi = pack2(vif.x, vif.x), vf = pack2(vif.y, vif.y);
                ULL vg = pack2(vgo.x, vgo.x), vo = pack2(vgo.y, vgo.y);
                const ulonglong2* hp1 = (const ulonglong2*)(hb1 + (size_t)k * (HP * 4));
                const ulonglong2* hp2 = (const ulonglong2*)(hb2 + (size_t)k * (HP * 4));
                {
                    ulonglong2 a0 = hp1[0], a1 = hp1[1];
                    ulonglong2 b0 = hp2[0], b1v = hp2[1];
                    #pragma unroll
                    for (int p = 0; p < 4; p++) {
                        ULL h1v = (p == 0) ? a0.x : (p == 1) ? a0.y : (p == 2) ? a1.x : a1.y;
                        ULL h2v = (p == 0) ? b0.x : (p == 1) ? b0.y : (p == 2) ? b1v.x : b1v.y;
                        acc[0][p] = fma2(h1v, wi, acc[0][p]);
                        acc[1][p] = fma2(h1v, wf, acc[1][p]);
                        acc[2][p] = fma2(h1v, wg, acc[2][p]);
                        acc[3][p] = fma2(h1v, wo, acc[3][p]);
                        acc[0][p] = fma2(h2v, vi, acc[0][p]);
                        acc[1][p] = fma2(h2v, vf, acc[1][p]);
                        acc[2][p] = fma2(h2v, vg, acc[2][p]);
                        acc[3][p] = fma2(h2v, vo, acc[3][p]);
                    }
                }
                {
                    ulonglong2 a2 = hp1[2], a3 = hp1[3];
                    ulonglong2 b2v = hp2[2], b3 = hp2[3];
                    #pragma unroll
                    for (int p = 4; p < 8; p++) {
                        ULL h1v = (p == 4) ? a2.x : (p == 5) ? a2.y : (p == 6) ? a3.x : a3.y;
                        ULL h2v = (p == 4) ? b2v.x : (p == 5) ? b2v.y : (p == 6) ? b3.x : b3.y;
                        acc[0][p] = fma2(h1v, wi, acc[0][p]);
                        acc[1][p] = fma2(h1v, wf, acc[1][p]);
                        acc[2][p] = fma2(h1v, wg, acc[2][p]);
                        acc[3][p] = fma2(h1v, wo, acc[3][p]);
                        acc[0][p] = fma2(h2v, vi, acc[0][p]);
                        acc[1][p] = fma2(h2v, vf, acc[1][p]);
                        acc[2][p] = fma2(h2v, vg, acc[2][p]);
                        acc[3][p] = fma2(h2v, vo, acc[3][p]);
                    }
                }
            }
        }
        __syncthreads();                                     // (3) GEMV2 + proj reads done
        #pragma unroll
        for (int p = 0; p < 8; p++) {
            float2 iv = unpack2(acc[0][p]);
            float2 fv = unpack2(acc[1][p]);
            float2 gv = unpack2(acc[2][p]);
            float2 ov = unpack2(acc[3][p]);
            int rr = r0 + 2 * p;
            float c0 = c2s[u * CP + rr], c1 = c2s[u * CP + rr + 1];
            c0 = sigf(fv.x) * c0 + sigf(iv.x) * tanhe(gv.x);
            c1 = sigf(fv.y) * c1 + sigf(iv.y) * tanhe(gv.y);
            c2s[u * CP + rr]     = c0;
            c2s[u * CP + rr + 1] = c1;
            float2 hn = make_float2(sigf(ov.x) * tanhe(c0), sigf(ov.y) * tanhe(c1));
            *(float2*)(h2s + u * HP + rr) = hn;
            __stcs(&out[((size_t)(rb + rr) * T_STEPS + t) * 256 + u],     hn.x);
            __stcs(&out[((size_t)(rb + rr + 1) * T_STEPS + t) * 256 + u], hn.y);
        }
        __syncthreads();                                     // (4) h2_new visible

        // ---- fused mu/logvar projection + sampler (320 threads, 8 rows each) ----
        if (pact) {
            ULL amu[4], alv[4];
            #pragma unroll
            for (int q = 0; q < 4; q++) { amu[q] = 0ULL; alv[q] = 0ULL; }
            const char* hb = (const char*)(h2s + pr0);
            #pragma unroll 2
            for (int k = 0; k < 256; k++) {
                float2 wv = g_pw2[k * 80 + pf];
                ULL wmu = pack2(wv.x, wv.x), wlv = pack2(wv.y, wv.y);
                const ulonglong2* hp = (const ulonglong2*)(hb + (size_t)k * (HP * 4));
                ulonglong2 h01 = hp[0], h23 = hp[1];
                #pragma unroll
                for (int q = 0; q < 4; q++) {
                    ULL hv = (q == 0) ? h01.x : (q == 1) ? h01.y : (q == 2) ? h23.x : h23.y;
                    amu[q] = fma2(hv, wmu, amu[q]);
                    alv[q] = fma2(hv, wlv, alv[q]);
                }
            }
            #pragma unroll
            for (int q = 0; q < 4; q++) {
                float2 mu = unpack2(amu[q]);
                float2 lv = unpack2(alv[q]);
                mu.x += pbmu; mu.y += pbmu;
                lv.x += pblv; lv.y += pblv;
                int r = pr0 + 2 * q;
                size_t b0 = ((size_t)(rb + r)     * T_STEPS + t) * 80 + pf;
                size_t b1 = ((size_t)(rb + r + 1) * T_STEPS + t) * 80 + pf;
                float e0 = __ldcs(&eps[b0]), e1 = __ldcs(&eps[b1]);
                __stcs(&out[41943040u + b0], mu.x);
                __stcs(&out[41943040u + b1], mu.y);
                __stcs(&out[55050240u + b0], lv.x);
                __stcs(&out[55050240u + b1], lv.y);
                __stcs(&out[68157440u + b0], e0 * __expf(0.5f * mu.x) + lv.x);
                __stcs(&out[68157440u + b1], e1 * __expf(0.5f * mu.y) + lv.y);
            }
        }
        // next h1s write is behind barrier (1) of t+1; h2s behind (3). Safe.
    }
}

extern "C" void kernel_launch(void* const* d_in, const int* in_sizes, int n_in,
                              void* d_out, int out_size) {
    // order: x, z1, z2, eps, W1, U1, b1, W2, U2, b2, Wmu, bmu, Wlv, blv
    const float* z1  = (const float*)d_in[1];
    const float* z2  = (const float*)d_in[2];
    const float* eps = (const float*)d_in[3];
    const float* W1  = (const float*)d_in[4];
    const float* U1  = (const float*)d_in[5];
    const float* b1  = (const float*)d_in[6];
    const float* W2  = (const float*)d_in[7];
    const float* U2  = (const float*)d_in[8];
    const float* b2  = (const float*)d_in[9];
    const float* Wmu = (const float*)d_in[10];
    const float* bmu = (const float*)d_in[11];
    const float* Wlv = (const float*)d_in[12];
    const float* blv = (const float*)d_in[13];
    float* out = (float*)d_out;

    cudaFuncSetAttribute(lstm_kernel, cudaFuncAttributeMaxDynamicSharedMemorySize, SMEM_BYTES);

    repack_kernel<<<256, 256>>>(W1, U1, W2, U2, Wmu, Wlv);
    xw1_kernel<<<1024, 256>>>(z1, z2, b1);
    lstm_kernel<<<256, 512, SMEM_BYTES>>>(b2, bmu, blv, eps, out);
}

// round 11
// speedup vs baseline: 1.9316x; 1.9316x over previous
#include <cuda_runtime.h>

// ---------------------------------------------------------------------------
// 2-layer LSTM decoder via TF32 tensor-core MMA (mma.sync.m16n8k8.tf32).
// 256 CTAs x 32 batch rows x 512 threads (16 warps). Per step:
//   GEMM1: h1old[32x256] @ U1[256x1024]   (+xw1, gates)  -> h1new
//   GEMM2: [h1new|h2old][32x512] @ [W2;U2][512x1024] (+b2, gates) -> h2new
//   PROJ : h2new[32x256] @ [Wmu|Wlv][256x160] (+bias) -> mu/lv -> sampler
// Weights pre-converted to tf32, gate-interleaved columns n' = unit*4+gate.
// B-fragments loaded directly from gmem; A (h) from smem; c-state in smem.
// ---------------------------------------------------------------------------

#define T_STEPS 20
#define AS 516     // A2 smem row stride (floats): (4r+c)%32 distinct -> conflict-free
#define CS 264     // c smem row stride
#define PS 164     // prj smem row stride

__device__ __forceinline__ float sigf(float x)  { return __fdividef(1.f, 1.f + __expf(-x)); }
__device__ __forceinline__ float tanhe(float x) { return __fdividef(2.f, 1.f + __expf(-2.f * x)) - 1.f; }
__device__ __forceinline__ unsigned tf32r(float x) {
    unsigned r; asm("cvt.rna.tf32.f32 %0, %1;" : "=r"(r) : "f"(x)); return r;
}
__device__ __forceinline__ void mma_tf32(float* d, unsigned a0, unsigned a1, unsigned a2,
                                         unsigned a3, unsigned b0, unsigned b1) {
    asm volatile(
        "mma.sync.aligned.m16n8k8.row.col.f32.tf32.tf32.f32 "
        "{%0,%1,%2,%3}, {%4,%5,%6,%7}, {%8,%9}, {%0,%1,%2,%3};"
        : "+f"(d[0]), "+f"(d[1]), "+f"(d[2]), "+f"(d[3])
        : "r"(a0), "r"(a1), "r"(a2), "r"(a3), "r"(b0), "r"(b1));
}

// Device-global weights (tf32 bit patterns) and scratch.
__device__ unsigned g_u1t [256 * 1024];     // U1  [k][n'], n' = unit*4+gate
__device__ unsigned g_w2t [512 * 1024];     // [W2;U2] [k][n']
__device__ unsigned g_pwt [256 * 160];      // [Wmu|Wlv] [k][f']
__device__ float    g_b2p [1024];           // b2 in n' order
__device__ float    g_pb  [160];            // [bmu|blv]
__device__ float4   g_w1q [64 * 256];       // W1 gate quads (fp32, for xw1)
__device__ float    g_xw1p[8192u * 1024u];  // xw1 [row][n'] fp32, bias folded

__global__ void repack_kernel(const float* __restrict__ W1, const float* __restrict__ U1,
                              const float* __restrict__ W2, const float* __restrict__ U2,
                              const float* __restrict__ Wmu, const float* __restrict__ Wlv,
                              const float* __restrict__ b2,  const float* __restrict__ bmu,
                              const float* __restrict__ blv) {
    int i = blockIdx.x * blockDim.x + threadIdx.x;   // 0 .. 512*1024-1
    int k2 = i >> 10, np = i & 1023;
    int u = np >> 2, g = np & 3;
    if (k2 < 256)
        g_u1t[i] = tf32r(U1[k2 * 1024 + g * 256 + u]);
    g_w2t[i] = tf32r(k2 < 256 ? W2[k2 * 1024 + g * 256 + u]
                              : U2[(k2 - 256) * 1024 + g * 256 + u]);
    if (k2 < 256 && np < 160)
        g_pwt[k2 * 160 + np] = tf32r(np < 80 ? Wmu[k2 * 80 + np] : Wlv[k2 * 80 + np - 80]);
    if (i < 64 * 256) {
        const float* r = W1 + (i >> 8) * 1024;
        int uu = i & 255;
        g_w1q[i] = make_float4(r[uu], r[256 + uu], r[512 + uu], r[768 + uu]);
    }
    if (i < 1024) g_b2p[i] = b2[(i & 3) * 256 + (i >> 2)];
    if (i < 160)  g_pb[i]  = (i < 80) ? bmu[i] : blv[i - 80];
}

__global__ void xw1_kernel(const float* __restrict__ z1, const float* __restrict__ z2,
                           const float* __restrict__ b1) {
    __shared__ float zt[8][64];
    const int tid = threadIdx.x;
    const int rb  = blockIdx.x * 8;
    for (int i = tid; i < 512; i += 256) {
        int r = i >> 6, k = i & 63;
        zt[r][k] = (k < 32) ? z1[(rb + r) * 32 + k] : z2[(rb + r) * 32 + (k - 32)];
    }
    __syncthreads();
    const int u = tid;
    float4 acc[8];
    #pragma unroll
    for (int r = 0; r < 8; r++) acc[r] = make_float4(0.f, 0.f, 0.f, 0.f);
    for (int k = 0; k < 64; k++) {
        float4 w = g_w1q[k * 256 + u];
        #pragma unroll
        for (int r = 0; r < 8; r++) {
            float zv = zt[r][k];
            acc[r].x += zv * w.x; acc[r].y += zv * w.y;
            acc[r].z += zv * w.z; acc[r].w += zv * w.w;
        }
    }
    float4 bq = make_float4(b1[u], b1[256 + u], b1[512 + u], b1[768 + u]);
    #pragma unroll
    for (int r = 0; r < 8; r++) {
        // n' layout: unit u's gates (i,f,g,o) at columns 4u..4u+3
        float4 o = make_float4(acc[r].x + bq.x, acc[r].y + bq.y,
                               acc[r].z + bq.z, acc[r].w + bq.w);
        *(float4*)(g_xw1p + (size_t)(rb + r) * 1024 + 4 * u) = o;
    }
}

// SMEM: A2 [32][AS] (cols 0-255 h1, 256-511 h2), c1s/c2s [32][CS], prj [32][PS]
#define SMEM_FLOATS (32 * AS + 2 * 32 * CS + 32 * PS)
#define SMEM_BYTES  (SMEM_FLOATS * 4)

// One GEMM block: acc[nt][mt][4] += A2[rows, acol+k] * B[k][cb + n], K = KC*8.
__device__ __forceinline__ void gemm_frag(
    float acc[8][2][4], const float* __restrict__ A2s, int acol,
    const unsigned* __restrict__ B, int KC, int cb, int lr, int q)
{
    #pragma unroll 1
    for (int kc = 0; kc < KC; kc++) {
        int kb = kc * 8;
        const unsigned* b0p = B + (size_t)(kb + q) * 1024 + cb + lr;
        const unsigned* b1p = b0p + 4 * 1024;
        unsigned a[2][4];
        #pragma unroll
        for (int mt = 0; mt < 2; mt++) {
            const float* ar = A2s + (mt * 16 + lr) * AS + acol + kb + q;
            a[mt][0] = __float_as_uint(ar[0]);
            a[mt][1] = __float_as_uint(ar[8 * AS]);
            a[mt][2] = __float_as_uint(ar[4]);
            a[mt][3] = __float_as_uint(ar[8 * AS + 4]);
        }
        #pragma unroll
        for (int nt = 0; nt < 8; nt++) {
            unsigned b0 = b0p[nt * 8];
            unsigned b1 = b1p[nt * 8];
            mma_tf32(acc[nt][0], a[0][0], a[0][1], a[0][2], a[0][3], b0, b1);
            mma_tf32(acc[nt][1], a[1][0], a[1][1], a[1][2], a[1][3], b0, b1);
        }
    }
}

__global__ void __launch_bounds__(512, 1) lstm_kernel(
    const float* __restrict__ eps, float* __restrict__ out)
{
    extern __shared__ float sm[];
    float* A2  = sm;                    // [32][AS]
    float* c1s = sm + 32 * AS;          // [32][CS]
    float* c2s = c1s + 32 * CS;
    float* prj = c2s + 32 * CS;         // [32][PS]

    const int tid  = threadIdx.x;
    const int w    = tid >> 5;
    const int lane = tid & 31;
    const int q    = lane & 3;
    const int lr   = lane >> 2;
    const int rb   = blockIdx.x * 32;
    const int wb   = w * 64;            // warp's n'-column base
    const bool qe  = !(q & 1);

    for (int i = tid; i < 32 * AS + 2 * 32 * CS; i += 512) sm[i] = 0.f;
    __syncthreads();

    float acc[8][2][4];

    for (int t = 0; t < T_STEPS; t++) {
        // ===================== GEMM1: h1old @ U1 =====================
        #pragma unroll
        for (int nt = 0; nt < 8; nt++)
            #pragma unroll
            for (int mt = 0; mt < 2; mt++)
                acc[nt][mt][0] = acc[nt][mt][1] = acc[nt][mt][2] = acc[nt][mt][3] = 0.f;
        gemm_frag(acc, A2, 0, g_u1t, 32, wb, lr, q);
        __syncthreads();                                 // (1) A2 h1 reads done

        // ----- epilogue 1: + xw1, gates, c1/h1 update -----
        #pragma unroll
        for (int nt = 0; nt < 8; nt++) {
            #pragma unroll
            for (int mt = 0; mt < 2; mt++) {
                float* d = acc[nt][mt];
                int cb = wb + nt * 8 + q * 2;
                int R0 = mt * 16 + lr, R1 = R0 + 8;
                float2 x0 = *(const float2*)(g_xw1p + (size_t)(rb + R0) * 1024 + cb);
                float2 x1 = *(const float2*)(g_xw1p + (size_t)(rb + R1) * 1024 + cb);
                d[0] += x0.x; d[1] += x0.y; d[2] += x1.x; d[3] += x1.y;
                float s0, s1, s2, s3;
                if (q & 1) { s0 = tanhe(d[0]); s1 = sigf(d[1]); s2 = tanhe(d[2]); s3 = sigf(d[3]); }
                else       { s0 = sigf(d[0]);  s1 = sigf(d[1]); s2 = sigf(d[2]);  s3 = sigf(d[3]); }
                float r0 = __shfl_xor_sync(~0u, s0, 1);
                float r1 = __shfl_xor_sync(~0u, s1, 1);
                float r2 = __shfl_xor_sync(~0u, s2, 1);
                float r3 = __shfl_xor_sync(~0u, s3, 1);
                if (qe) {   // owns (i,f); receives (g,o)
                    int u = w * 16 + nt * 2 + (q >> 1);
                    float cn0 = s1 * c1s[R0 * CS + u] + s0 * r0;
                    c1s[R0 * CS + u] = cn0;
                    A2[R0 * AS + u] = __uint_as_float(tf32r(r1 * tanhe(cn0)));
                    float cn1 = s3 * c1s[R1 * CS + u] + s2 * r2;
                    c1s[R1 * CS + u] = cn1;
                    A2[R1 * AS + u] = __uint_as_float(tf32r(r3 * tanhe(cn1)));
                }
            }
        }
        __syncthreads();                                 // (2) h1new visible

        // ============ GEMM2: [h1new|h2old] @ [W2;U2] ============
        #pragma unroll
        for (int nt = 0; nt < 8; nt++)
            #pragma unroll
            for (int mt = 0; mt < 2; mt++)
                acc[nt][mt][0] = acc[nt][mt][1] = acc[nt][mt][2] = acc[nt][mt][3] = 0.f;
        gemm_frag(acc, A2, 0, g_w2t, 64, wb, lr, q);
        __syncthreads();                                 // (3) A2 reads done

        // ----- epilogue 2: + b2, gates, c2/h2 update, h2 -> out -----
        #pragma unroll
        for (int nt = 0; nt < 8; nt++) {
            #pragma unroll
            for (int mt = 0; mt < 2; mt++) {
                float* d = acc[nt][mt];
                int cb = wb + nt * 8 + q * 2;
                int R0 = mt * 16 + lr, R1 = R0 + 8;
                float2 bb = *(const float2*)(g_b2p + cb);
                d[0] += bb.x; d[1] += bb.y; d[2] += bb.x; d[3] += bb.y;
                float s0, s1, s2, s3;
                if (q & 1) { s0 = tanhe(d[0]); s1 = sigf(d[1]); s2 = tanhe(d[2]); s3 = sigf(d[3]); }
                else       { s0 = sigf(d[0]);  s1 = sigf(d[1]); s2 = sigf(d[2]);  s3 = sigf(d[3]); }
                float r0 = __shfl_xor_sync(~0u, s0, 1);
                float r1 = __shfl_xor_sync(~0u, s1, 1);
                float r2 = __shfl_xor_sync(~0u, s2, 1);
                float r3 = __shfl_xor_sync(~0u, s3, 1);
                if (qe) {
                    int u = w * 16 + nt * 2 + (q >> 1);
                    float cn0 = s1 * c2s[R0 * CS + u] + s0 * r0;
                    c2s[R0 * CS + u] = cn0;
                    float h0 = r1 * tanhe(cn0);
                    A2[R0 * AS + 256 + u] = __uint_as_float(tf32r(h0));
                    float cn1 = s3 * c2s[R1 * CS + u] + s2 * r2;
                    c2s[R1 * CS + u] = cn1;
                    float h1 = r3 * tanhe(cn1);
                    A2[R1 * AS + 256 + u] = __uint_as_float(tf32r(h1));
                    out[((size_t)(rb + R0) * T_STEPS + t) * 256 + u] = h0;
                    out[((size_t)(rb + R1) * T_STEPS + t) * 256 + u] = h1;
                }
            }
        }
        __syncthreads();                                 // (4) h2new visible

        // =============== PROJ: h2new @ [Wmu|Wlv] (warps 0-9) ===============
        if (w < 10) {
            float pa[2][2][4];
            #pragma unroll
            for (int nt = 0; nt < 2; nt++)
                #pragma unroll
                for (int mt = 0; mt < 2; mt++)
                    pa[nt][mt][0] = pa[nt][mt][1] = pa[nt][mt][2] = pa[nt][mt][3] = 0.f;
            #pragma unroll 1
            for (int kc = 0; kc < 32; kc++) {
                int kb = kc * 8;
                const unsigned* b0p = g_pwt + (kb + q) * 160 + w * 16 + lr;
                const unsigned* b1p = b0p + 4 * 160;
                unsigned a[2][4];
                #pragma unroll
                for (int mt = 0; mt < 2; mt++) {
                    const float* ar = A2 + (mt * 16 + lr) * AS + 256 + kb + q;
                    a[mt][0] = __float_as_uint(ar[0]);
                    a[mt][1] = __float_as_uint(ar[8 * AS]);
                    a[mt][2] = __float_as_uint(ar[4]);
                    a[mt][3] = __float_as_uint(ar[8 * AS + 4]);
                }
                #pragma unroll
                for (int nt = 0; nt < 2; nt++) {
                    unsigned b0 = b0p[nt * 8];
                    unsigned b1 = b1p[nt * 8];
                    mma_tf32(pa[nt][0], a[0][0], a[0][1], a[0][2], a[0][3], b0, b1);
                    mma_tf32(pa[nt][1], a[1][0], a[1][1], a[1][2], a[1][3], b0, b1);
                }
            }
            #pragma unroll
            for (int nt = 0; nt < 2; nt++) {
                #pragma unroll
                for (int mt = 0; mt < 2; mt++) {
                    int col = w * 16 + nt * 8 + q * 2;
                    int R0 = mt * 16 + lr, R1 = R0 + 8;
                    float2 pb = *(const float2*)(g_pb + col);
                    prj[R0 * PS + col]     = pa[nt][mt][0] + pb.x;
                    prj[R0 * PS + col + 1] = pa[nt][mt][1] + pb.y;
                    prj[R1 * PS + col]     = pa[nt][mt][2] + pb.x;
                    prj[R1 * PS + col + 1] = pa[nt][mt][3] + pb.y;
                }
            }
        }
        __syncthreads();                                 // (5) prj ready

        // ---- sampler: 512 threads x 5 = 32 rows x 80 features ----
        #pragma unroll
        for (int j = 0; j < 5; j++) {
            int i = tid + j * 512;
            int r = i / 80, f = i - r * 80;
            float mu = prj[r * PS + f];
            float lv = prj[r * PS + f + 80];
            size_t base = ((size_t)(rb + r) * T_STEPS + t) * 80 + f;
            float e = eps[base];
            out[41943040u + base] = mu;
            out[55050240u + base] = lv;
            out[68157440u + base] = e * __expf(0.5f * mu) + lv;
        }
        // next write to prj is behind 4 barriers of step t+1; A2/c writes behind (1)/(3).
    }
}

extern "C" void kernel_launch(void* const* d_in, const int* in_sizes, int n_in,
                              void* d_out, int out_size) {
    // order: x, z1, z2, eps, W1, U1, b1, W2, U2, b2, Wmu, bmu, Wlv, blv
    const float* z1  = (const float*)d_in[1];
    const float* z2  = (const float*)d_in[2];
    const float* eps = (const float*)d_in[3];
    const float* W1  = (const float*)d_in[4];
    const float* U1  = (const float*)d_in[5];
    const float* b1  = (const float*)d_in[6];
    const float* W2  = (const float*)d_in[7];
    const float* U2  = (const float*)d_in[8];
    const float* b2  = (const float*)d_in[9];
    const float* Wmu = (const float*)d_in[10];
    const float* bmu = (const float*)d_in[11];
    const float* Wlv = (const float*)d_in[12];
    const float* blv = (const float*)d_in[13];
    float* out = (float*)d_out;

    cudaFuncSetAttribute(lstm_kernel, cudaFuncAttributeMaxDynamicSharedMemorySize, SMEM_BYTES);

    repack_kernel<<<512, 1024>>>(W1, U1, W2, U2, Wmu, Wlv, b2, bmu, blv);
    xw1_kernel<<<1024, 256>>>(z1, z2, b1);
    lstm_kernel<<<256, 512, SMEM_BYTES>>>(eps, out);
}